// round 2
// baseline (speedup 1.0000x reference)
#include <cuda_runtime.h>
#include <stdint.h>

// out[n,o] = -|eta| * sum_i |x[n,i] - w[o,i]|
// N=2048, K=1024, O=2048, fp32.
//
// Pipeline: pre-pass negates w into g_negw (device scratch). Main kernel:
// cp.async double-buffered smem tiles, packed f32x2 adds (fma pipe) +
// LOP3 sign-clear abs (alu pipe). Issue-port-limited design: minimize
// non-pipe instructions.

#define N_ROWS 2048
#define K_DIM  1024
#define O_COLS 2048

#define TN 128
#define TO 64
#define KT 32
#define SS 36                        // row stride (floats); 144B keeps 16B reads conflict-free
#define NTILES (K_DIM / KT)          // 32
#define BUF_FLOATS ((TN + TO) * SS)  // 6912 floats = 27648 B per buffer
#define SMEM_BYTES (2 * BUF_FLOATS * 4)  // 55296 B

__device__ float g_negw[O_COLS * K_DIM];   // 8 MB scratch: -w

__global__ void negw_kernel(const float* __restrict__ w)
{
    int i = blockIdx.x * blockDim.x + threadIdx.x;   // float4 index
    float4 v = ((const float4*)w)[i];
    float4 r;
    r.x = -v.x; r.y = -v.y; r.z = -v.z; r.w = -v.w;
    ((float4*)g_negw)[i] = r;
}

__device__ __forceinline__ void cp16(float* dst, const float* src)
{
    unsigned s = (unsigned)__cvta_generic_to_shared(dst);
    asm volatile("cp.async.cg.shared.global [%0], [%1], 16;"
                 :: "r"(s), "l"(src) : "memory");
}
__device__ __forceinline__ void cp_commit()
{
    asm volatile("cp.async.commit_group;" ::: "memory");
}
__device__ __forceinline__ void cp_wait_all()
{
    asm volatile("cp.async.wait_group 0;" ::: "memory");
}

// packed: d = a + b (b pre-negated); d = |d| per half; acc += d
#define STEP(xr, wr, a) do {                                             \
    uint64_t d_;                                                         \
    asm("add.rn.f32x2 %0, %1, %2;" : "=l"(d_) : "l"(xr), "l"(wr));       \
    asm("{\n\t"                                                          \
        ".reg .b32 lo, hi;\n\t"                                          \
        "mov.b64 {lo, hi}, %0;\n\t"                                      \
        "and.b32 lo, lo, 0x7fffffff;\n\t"                                \
        "and.b32 hi, hi, 0x7fffffff;\n\t"                                \
        "mov.b64 %0, {lo, hi};\n\t"                                      \
        "}" : "+l"(d_));                                                 \
    asm("add.rn.f32x2 %0, %0, %1;" : "+l"(a) : "l"(d_));                 \
} while (0)

__global__ __launch_bounds__(256, 2)
void adder_linear_kernel(const float* __restrict__ x,
                         const float* __restrict__ eta,
                         float* __restrict__ out)
{
    extern __shared__ float smem[];
    float* buf0 = smem;
    float* buf1 = smem + BUF_FLOATS;

    const int tid    = threadIdx.x;
    const int wid    = tid >> 5;
    const int lane   = tid & 31;
    const int warp_n = wid & 1;
    const int warp_o = wid >> 1;
    const int lane_n = lane & 7;
    const int lane_o = lane >> 3;

    const int n0 = blockIdx.y * TN;
    const int o0 = blockIdx.x * TO;

    const int tn = warp_n * 64 + lane_n;   // + i*8, i=0..7
    const int to = warp_o * 16 + lane_o;   // + j*4, j=0..3

    uint64_t acc[8][4];
    #pragma unroll
    for (int i = 0; i < 8; i++)
        #pragma unroll
        for (int j = 0; j < 4; j++)
            acc[i][j] = 0ull;

    // ---- prefetch helper (4 x-chunks + 2 w-chunks per thread) ----
    auto prefetch = [&](float* buf, int kt) {
        float* sx = buf;
        float* sw = buf + TN * SS;
        #pragma unroll
        for (int it = 0; it < 4; it++) {
            int idx = tid + 256 * it;          // 0..1023
            int r = idx >> 3, q = idx & 7;
            cp16(&sx[r * SS + q * 4],
                 &x[(size_t)(n0 + r) * K_DIM + kt + q * 4]);
        }
        #pragma unroll
        for (int it = 0; it < 2; it++) {
            int idx = tid + 256 * it;          // 0..511
            int r = idx >> 3, q = idx & 7;
            cp16(&sw[r * SS + q * 4],
                 &g_negw[(size_t)(o0 + r) * K_DIM + kt + q * 4]);
        }
    };

    prefetch(buf0, 0);
    cp_commit();

    for (int t = 0; t < NTILES; t++) {
        cp_wait_all();          // tile t landed
        __syncthreads();        // all threads done with buffer being refilled next

        if (t + 1 < NTILES) {
            prefetch((t & 1) ? buf0 : buf1, (t + 1) * KT);
            cp_commit();
        }

        const float* sb = (t & 1) ? buf1 : buf0;
        const float* xb = sb + tn * SS;
        const float* wb = sb + TN * SS + to * SS;

        #pragma unroll 2
        for (int kk = 0; kk < KT; kk += 4) {
            uint64_t wq[4][2];
            #pragma unroll
            for (int j = 0; j < 4; j++) {
                ulonglong2 v = *(const ulonglong2*)(wb + j * 4 * SS + kk);
                wq[j][0] = v.x; wq[j][1] = v.y;
            }
            #pragma unroll
            for (int h = 0; h < 2; h++) {
                uint64_t xq[4][2];
                #pragma unroll
                for (int i2 = 0; i2 < 4; i2++) {
                    ulonglong2 v =
                        *(const ulonglong2*)(xb + (h * 4 + i2) * 8 * SS + kk);
                    xq[i2][0] = v.x; xq[i2][1] = v.y;
                }
                #pragma unroll
                for (int i2 = 0; i2 < 4; i2++) {
                    #pragma unroll
                    for (int j = 0; j < 4; j++) {
                        STEP(xq[i2][0], wq[j][0], acc[h * 4 + i2][j]);
                        STEP(xq[i2][1], wq[j][1], acc[h * 4 + i2][j]);
                    }
                }
            }
        }
    }

    const float scale = -fabsf(eta[0]);

    #pragma unroll
    for (int i = 0; i < 8; i++) {
        int n = n0 + tn + i * 8;
        #pragma unroll
        for (int j = 0; j < 4; j++) {
            int o = o0 + to + j * 4;
            float lo, hi;
            asm("mov.b64 {%0, %1}, %2;" : "=f"(lo), "=f"(hi) : "l"(acc[i][j]));
            out[(size_t)n * O_COLS + o] = (lo + hi) * scale;
        }
    }
}

extern "C" void kernel_launch(void* const* d_in, const int* in_sizes, int n_in,
                              void* d_out, int out_size)
{
    const float* x   = (const float*)d_in[0];   // [2048, 1024]
    const float* w   = (const float*)d_in[1];   // [2048, 1024]
    const float* eta = (const float*)d_in[2];   // [1]
    float* out = (float*)d_out;                 // [2048, 2048]

    cudaFuncSetAttribute(adder_linear_kernel,
                         cudaFuncAttributeMaxDynamicSharedMemorySize,
                         SMEM_BYTES);

    // pre-pass: g_negw = -w   (2048*1024 floats = 524288 float4)
    negw_kernel<<<O_COLS * K_DIM / 4 / 256, 256>>>(w);

    dim3 grid(O_COLS / TO, N_ROWS / TN);   // (32, 16)
    adder_linear_kernel<<<grid, 256, SMEM_BYTES>>>(x, eta, out);
}

// round 3
// speedup vs baseline: 1.1620x; 1.1620x over previous
#include <cuda_runtime.h>
#include <stdint.h>

// out[n,o] = -|eta| * sum_i |x[n,i] - w[o,i]|
// N=2048, K=1024, O=2048, fp32.
//
// Latency-tolerance build: 16 outputs/thread (32 acc regs), 3 CTAs/SM
// (24 warps), cp.async double-buffered 64x64 tiles, packed f32x2 adds
// (fma pipe) + LOP3 sign-clear abs (alu pipe).

#define N_ROWS 2048
#define K_DIM  1024
#define O_COLS 2048

#define TN 64
#define TO 64
#define KT 32
#define SS 36                        // row stride (floats); conflict-free for 8B/16B reads
#define NTILES (K_DIM / KT)          // 32
#define BUF_FLOATS ((TN + TO) * SS)  // 4608 floats = 18432 B per buffer

__device__ float g_negw[O_COLS * K_DIM];   // 8 MB scratch: -w

__global__ void negw_kernel(const float* __restrict__ w)
{
    int i = blockIdx.x * blockDim.x + threadIdx.x;   // float4 index
    float4 v = ((const float4*)w)[i];
    float4 r;
    r.x = -v.x; r.y = -v.y; r.z = -v.z; r.w = -v.w;
    ((float4*)g_negw)[i] = r;
}

__device__ __forceinline__ void cp16(float* dst, const float* src)
{
    unsigned s = (unsigned)__cvta_generic_to_shared(dst);
    asm volatile("cp.async.cg.shared.global [%0], [%1], 16;"
                 :: "r"(s), "l"(src) : "memory");
}
__device__ __forceinline__ void cp_commit()
{
    asm volatile("cp.async.commit_group;" ::: "memory");
}
__device__ __forceinline__ void cp_wait_all()
{
    asm volatile("cp.async.wait_group 0;" ::: "memory");
}

// packed: d = x + (-w); d = |d| per half; acc += d
#define STEP(xr, wr, a) do {                                             \
    uint64_t d_;                                                         \
    asm("add.rn.f32x2 %0, %1, %2;" : "=l"(d_) : "l"(xr), "l"(wr));       \
    asm("{\n\t"                                                          \
        ".reg .b32 lo, hi;\n\t"                                          \
        "mov.b64 {lo, hi}, %0;\n\t"                                      \
        "and.b32 lo, lo, 0x7fffffff;\n\t"                                \
        "and.b32 hi, hi, 0x7fffffff;\n\t"                                \
        "mov.b64 %0, {lo, hi};\n\t"                                      \
        "}" : "+l"(d_));                                                 \
    asm("add.rn.f32x2 %0, %0, %1;" : "+l"(a) : "l"(d_));                 \
} while (0)

__global__ __launch_bounds__(256, 3)
void adder_linear_kernel(const float* __restrict__ x,
                         const float* __restrict__ eta,
                         float* __restrict__ out)
{
    __shared__ float smem[2 * BUF_FLOATS];   // 36864 B -> 3 CTAs/SM

    const int tid    = threadIdx.x;
    const int wid    = tid >> 5;
    const int lane   = tid & 31;
    const int warp_n = wid & 1;          // 0..1
    const int warp_o = wid >> 1;         // 0..3
    const int lane_n = lane & 7;         // 0..7
    const int lane_o = lane >> 3;        // 0..3

    const int n0 = blockIdx.y * TN;
    const int o0 = blockIdx.x * TO;

    // thread outputs: n = n0 + tn + i*8 (i<4), o = o0 + to + j*4 (j<4)
    const int tn = warp_n * 32 + lane_n;
    const int to = warp_o * 16 + lane_o;

    uint64_t acc[4][4];
    #pragma unroll
    for (int i = 0; i < 4; i++)
        #pragma unroll
        for (int j = 0; j < 4; j++)
            acc[i][j] = 0ull;

    // prefetch: 2 x-chunks + 2 w-chunks of 16B per thread
    auto prefetch = [&](float* buf, int kt) {
        float* sx = buf;
        float* sw = buf + TN * SS;
        #pragma unroll
        for (int it = 0; it < 2; it++) {
            int idx = tid + 256 * it;          // 0..511
            int r = idx >> 3, q = idx & 7;
            cp16(&sx[r * SS + q * 4],
                 &x[(size_t)(n0 + r) * K_DIM + kt + q * 4]);
        }
        #pragma unroll
        for (int it = 0; it < 2; it++) {
            int idx = tid + 256 * it;          // 0..511
            int r = idx >> 3, q = idx & 7;
            cp16(&sw[r * SS + q * 4],
                 &g_negw[(size_t)(o0 + r) * K_DIM + kt + q * 4]);
        }
    };

    prefetch(smem, 0);
    cp_commit();

    for (int t = 0; t < NTILES; t++) {
        cp_wait_all();          // tile t data landed
        __syncthreads();        // everyone done computing on the other buffer

        if (t + 1 < NTILES) {
            prefetch((t & 1) ? smem : smem + BUF_FLOATS, (t + 1) * KT);
            cp_commit();
        }

        const float* sb = (t & 1) ? smem + BUF_FLOATS : smem;
        const float* xb = sb + tn * SS;
        const float* wb = sb + TN * SS + to * SS;

        #pragma unroll 4
        for (int kk = 0; kk < KT; kk += 4) {
            uint64_t wq[4][2], xq[4][2];
            #pragma unroll
            for (int j = 0; j < 4; j++) {
                ulonglong2 v = *(const ulonglong2*)(wb + j * 4 * SS + kk);
                wq[j][0] = v.x; wq[j][1] = v.y;
            }
            #pragma unroll
            for (int i = 0; i < 4; i++) {
                ulonglong2 v = *(const ulonglong2*)(xb + i * 8 * SS + kk);
                xq[i][0] = v.x; xq[i][1] = v.y;
            }
            #pragma unroll
            for (int i = 0; i < 4; i++) {
                #pragma unroll
                for (int j = 0; j < 4; j++) {
                    STEP(xq[i][0], wq[j][0], acc[i][j]);
                    STEP(xq[i][1], wq[j][1], acc[i][j]);
                }
            }
        }
    }

    const float scale = -fabsf(eta[0]);

    #pragma unroll
    for (int i = 0; i < 4; i++) {
        int n = n0 + tn + i * 8;
        #pragma unroll
        for (int j = 0; j < 4; j++) {
            int o = o0 + to + j * 4;
            float lo, hi;
            asm("mov.b64 {%0, %1}, %2;" : "=f"(lo), "=f"(hi) : "l"(acc[i][j]));
            out[(size_t)n * O_COLS + o] = (lo + hi) * scale;
        }
    }
}

extern "C" void kernel_launch(void* const* d_in, const int* in_sizes, int n_in,
                              void* d_out, int out_size)
{
    const float* x   = (const float*)d_in[0];   // [2048, 1024]
    const float* w   = (const float*)d_in[1];   // [2048, 1024]
    const float* eta = (const float*)d_in[2];   // [1]
    float* out = (float*)d_out;                 // [2048, 2048]

    // pre-pass: g_negw = -w
    negw_kernel<<<O_COLS * K_DIM / 4 / 256, 256>>>(w);

    dim3 grid(O_COLS / TO, N_ROWS / TN);        // (32, 32) = 1024 blocks
    adder_linear_kernel<<<grid, 256>>>(x, eta, out);
}

// round 4
// speedup vs baseline: 1.1824x; 1.0176x over previous
#include <cuda_runtime.h>
#include <stdint.h>

// out[n,o] = -|eta| * sum_i |x[n,i] - w[o,i]|
// N=2048, K=1024, O=2048, fp32.
//
// Round 4: register-level software pipeline over the smem loads.
// Each 4-k body prefetches the NEXT body's xq/wq registers before doing the
// current body's 128 packed compute issues -> LDS latency covered in-warp,
// no per-body convoy stall. 16 outputs/thread, 3 CTAs/SM, cp.async
// double-buffered 64x64 tiles, packed f32x2 adds (fma) + LOP3 abs (alu).

#define N_ROWS 2048
#define K_DIM  1024
#define O_COLS 2048

#define TN 64
#define TO 64
#define KT 32
#define SS 36                        // row stride (floats); conflict-free
#define NTILES (K_DIM / KT)          // 32
#define NBODY  (KT / 4)              // 8 bodies per tile
#define BUF_FLOATS ((TN + TO) * SS)  // 4608 floats = 18432 B per buffer

__device__ float g_negw[O_COLS * K_DIM];   // 8 MB scratch: -w

__global__ void negw_kernel(const float* __restrict__ w)
{
    int i = blockIdx.x * blockDim.x + threadIdx.x;   // float4 index
    float4 v = ((const float4*)w)[i];
    float4 r;
    r.x = -v.x; r.y = -v.y; r.z = -v.z; r.w = -v.w;
    ((float4*)g_negw)[i] = r;
}

__device__ __forceinline__ void cp16(float* dst, const float* src)
{
    unsigned s = (unsigned)__cvta_generic_to_shared(dst);
    asm volatile("cp.async.cg.shared.global [%0], [%1], 16;"
                 :: "r"(s), "l"(src) : "memory");
}
__device__ __forceinline__ void cp_commit()
{
    asm volatile("cp.async.commit_group;" ::: "memory");
}
__device__ __forceinline__ void cp_wait_all()
{
    asm volatile("cp.async.wait_group 0;" ::: "memory");
}

// packed: d = x + (-w); d = |d| per half; acc += d
#define STEP(xr, wr, a) do {                                             \
    uint64_t d_;                                                         \
    asm("add.rn.f32x2 %0, %1, %2;" : "=l"(d_) : "l"(xr), "l"(wr));       \
    asm("{\n\t"                                                          \
        ".reg .b32 lo, hi;\n\t"                                          \
        "mov.b64 {lo, hi}, %0;\n\t"                                      \
        "and.b32 lo, lo, 0x7fffffff;\n\t"                                \
        "and.b32 hi, hi, 0x7fffffff;\n\t"                                \
        "mov.b64 %0, {lo, hi};\n\t"                                      \
        "}" : "+l"(d_));                                                 \
    asm("add.rn.f32x2 %0, %0, %1;" : "+l"(a) : "l"(d_));                 \
} while (0)

// load register set s for k-offset kk within the current tile
#define LOADSET(s, kk) do {                                              \
    _Pragma("unroll")                                                    \
    for (int j = 0; j < 4; j++) {                                        \
        ulonglong2 v = *(const ulonglong2*)(wb + j * 4 * SS + (kk));     \
        wq[s][j][0] = v.x; wq[s][j][1] = v.y;                            \
    }                                                                    \
    _Pragma("unroll")                                                    \
    for (int i = 0; i < 4; i++) {                                        \
        ulonglong2 v = *(const ulonglong2*)(xb + i * 8 * SS + (kk));     \
        xq[s][i][0] = v.x; xq[s][i][1] = v.y;                            \
    }                                                                    \
} while (0)

#define COMPUTE(s) do {                                                  \
    _Pragma("unroll")                                                    \
    for (int i = 0; i < 4; i++) {                                        \
        _Pragma("unroll")                                                \
        for (int j = 0; j < 4; j++) {                                    \
            STEP(xq[s][i][0], wq[s][j][0], acc[i][j]);                   \
            STEP(xq[s][i][1], wq[s][j][1], acc[i][j]);                   \
        }                                                                \
    }                                                                    \
} while (0)

__global__ __launch_bounds__(256, 3)
void adder_linear_kernel(const float* __restrict__ x,
                         const float* __restrict__ eta,
                         float* __restrict__ out)
{
    __shared__ float smem[2 * BUF_FLOATS];   // 36864 B -> 3 CTAs/SM

    const int tid    = threadIdx.x;
    const int wid    = tid >> 5;
    const int lane   = tid & 31;
    const int warp_n = wid & 1;          // 0..1
    const int warp_o = wid >> 1;         // 0..3
    const int lane_n = lane & 7;         // 0..7
    const int lane_o = lane >> 3;        // 0..3

    const int n0 = blockIdx.y * TN;
    const int o0 = blockIdx.x * TO;

    // thread outputs: n = n0 + tn + i*8 (i<4), o = o0 + to + j*4 (j<4)
    const int tn = warp_n * 32 + lane_n;
    const int to = warp_o * 16 + lane_o;

    uint64_t acc[4][4];
    #pragma unroll
    for (int i = 0; i < 4; i++)
        #pragma unroll
        for (int j = 0; j < 4; j++)
            acc[i][j] = 0ull;

    auto prefetch = [&](float* buf, int kt) {
        float* sxp = buf;
        float* swp = buf + TN * SS;
        #pragma unroll
        for (int it = 0; it < 2; it++) {
            int idx = tid + 256 * it;          // 0..511
            int r = idx >> 3, q = idx & 7;
            cp16(&sxp[r * SS + q * 4],
                 &x[(size_t)(n0 + r) * K_DIM + kt + q * 4]);
        }
        #pragma unroll
        for (int it = 0; it < 2; it++) {
            int idx = tid + 256 * it;
            int r = idx >> 3, q = idx & 7;
            cp16(&swp[r * SS + q * 4],
                 &g_negw[(size_t)(o0 + r) * K_DIM + kt + q * 4]);
        }
    };

    prefetch(smem, 0);
    cp_commit();

    uint64_t xq[2][4][2], wq[2][4][2];

    for (int t = 0; t < NTILES; t++) {
        cp_wait_all();          // tile t landed
        __syncthreads();        // other buffer free for refill

        if (t + 1 < NTILES) {
            prefetch((t & 1) ? smem : smem + BUF_FLOATS, (t + 1) * KT);
            cp_commit();
        }

        const float* sb = (t & 1) ? smem + BUF_FLOATS : smem;
        const float* xb = sb + tn * SS;
        const float* wb = sb + TN * SS + to * SS;

        LOADSET(0, 0);                        // prime the pipeline
        #pragma unroll
        for (int b = 0; b < NBODY; b++) {
            const int cur = b & 1;
            if (b + 1 < NBODY)
                LOADSET(cur ^ 1, (b + 1) * 4);  // next body's regs in flight
            COMPUTE(cur);                        // 128 issues cover LDS latency
        }
    }

    const float scale = -fabsf(eta[0]);

    #pragma unroll
    for (int i = 0; i < 4; i++) {
        int n = n0 + tn + i * 8;
        #pragma unroll
        for (int j = 0; j < 4; j++) {
            int o = o0 + to + j * 4;
            float lo, hi;
            asm("mov.b64 {%0, %1}, %2;" : "=f"(lo), "=f"(hi) : "l"(acc[i][j]));
            out[(size_t)n * O_COLS + o] = (lo + hi) * scale;
        }
    }
}

extern "C" void kernel_launch(void* const* d_in, const int* in_sizes, int n_in,
                              void* d_out, int out_size)
{
    const float* x   = (const float*)d_in[0];   // [2048, 1024]
    const float* w   = (const float*)d_in[1];   // [2048, 1024]
    const float* eta = (const float*)d_in[2];   // [1]
    float* out = (float*)d_out;                 // [2048, 2048]

    // pre-pass: g_negw = -w
    negw_kernel<<<O_COLS * K_DIM / 4 / 256, 256>>>(w);

    dim3 grid(O_COLS / TO, N_ROWS / TN);        // (32, 32) = 1024 blocks
    adder_linear_kernel<<<grid, 256>>>(x, eta, out);
}